// round 3
// baseline (speedup 1.0000x reference)
#include <cuda_runtime.h>

#define BB 4
#define HH 512
#define WW 512
#define HW (HH*WW)
#define NPIX (BB*HW)             // 1048576
#define T1 17                    // T_MAX + 1
#define CAP (NPIX/2 + 64)        // max possible component count
#define NBLK 128
#define NTHR 1024
#define NTOT (NBLK*NTHR)         // 131072

#define NF 1048576.0f
#define SP0F ((float)0.6931471805599453)
#define C1F  ((float)(1.3132616875182228 - 0.6931471805599453))   // SP1 - SP0
#define C2F  ((float)(0.7310585786300049 - 0.5))                  // S1 - 0.5

// ---------------- device scratch (static, no allocation) ----------------
__device__ __align__(16) int g_par[NPIX];     // UF parent; -1 = background
__device__ int g_cidx[NPIX];                  // root pixel -> compact idx
__device__ int g_orig[CAP];                   // compact idx -> root pixel
__device__ int g_cnt_c[CAP];                  // component sizes
__device__ int g_intert[(size_t)T1 * CAP];    // transposed confusion [t][c]
__device__ int g_cnt_t[T1];
__device__ int g_m;
__device__ float g_bce_sum, g_p_sum, g_pt_sum, g_t_sum;
__device__ unsigned long long g_mk[T1];
__device__ unsigned int g_bar_count;          // zero-init; self-restoring
__device__ unsigned int g_bar_gen;

// ---------------- grid barrier (all NBLK blocks co-resident) ----------------
__device__ __forceinline__ void grid_barrier() {
    __syncthreads();
    if (threadIdx.x == 0) {
        unsigned gen = *(volatile unsigned*)&g_bar_gen;
        __threadfence();
        unsigned arr = atomicAdd(&g_bar_count, 1u);
        if (arr == NBLK - 1) {
            atomicExch(&g_bar_count, 0u);
            __threadfence();
            atomicExch(&g_bar_gen, gen + 1u);
        } else {
            while (*(volatile unsigned*)&g_bar_gen == gen) __nanosleep(32);
        }
        __threadfence();
    }
    __syncthreads();
}

// ---------------- union-find (max-root, path halving; ECL-CC pattern) -------
__device__ __forceinline__ int uf_find(int x) {
    volatile int* par = (volatile int*)g_par;
    int p = par[x];
    while (p != x) {
        int gp = par[p];
        if (gp != p) par[x] = gp;     // halving: stored value always an ancestor
        x = gp;
        p = par[x];
    }
    return x;
}

__device__ __forceinline__ void uf_unite(int a, int b) {
    int ra = uf_find(a);
    int rb = uf_find(b);
    while (ra != rb) {
        if (ra > rb) { int t = ra; ra = rb; rb = t; }   // attach smaller under bigger
        int old = atomicMax(&g_par[ra], rb);
        if (old == ra) break;                            // ra was root: linked
        ra = uf_find(old);
        rb = uf_find(rb);
    }
}

// ---------------- block reductions (32 warps) ----------------
__device__ __forceinline__ float4 blockReduceSum4(float4 v) {
    __shared__ float4 s[32];
    unsigned m = 0xFFFFFFFFu;
    #pragma unroll
    for (int o = 16; o; o >>= 1) {
        v.x += __shfl_down_sync(m, v.x, o);
        v.y += __shfl_down_sync(m, v.y, o);
        v.z += __shfl_down_sync(m, v.z, o);
        v.w += __shfl_down_sync(m, v.w, o);
    }
    int lane = threadIdx.x & 31, wid = threadIdx.x >> 5;
    if (lane == 0) s[wid] = v;
    __syncthreads();
    if (wid == 0) {
        v = (lane < (NTHR >> 5)) ? s[lane] : make_float4(0.f, 0.f, 0.f, 0.f);
        #pragma unroll
        for (int o = 16; o; o >>= 1) {
            v.x += __shfl_down_sync(m, v.x, o);
            v.y += __shfl_down_sync(m, v.y, o);
            v.z += __shfl_down_sync(m, v.z, o);
            v.w += __shfl_down_sync(m, v.w, o);
        }
    }
    return v;
}

__device__ __forceinline__ unsigned long long blockReduceMinU64(unsigned long long v) {
    __shared__ unsigned long long s[32];
    unsigned m = 0xFFFFFFFFu;
    #pragma unroll
    for (int o = 16; o; o >>= 1) {
        unsigned long long o2 = __shfl_down_sync(m, v, o);
        v = (o2 < v) ? o2 : v;
    }
    int lane = threadIdx.x & 31, wid = threadIdx.x >> 5;
    if (lane == 0) s[wid] = v;
    __syncthreads();
    if (wid == 0) {
        v = (lane < (NTHR >> 5)) ? s[lane] : ~0ULL;
        #pragma unroll
        for (int o = 16; o; o >>= 1) {
            unsigned long long o2 = __shfl_down_sync(m, v, o);
            v = (o2 < v) ? o2 : v;
        }
    }
    return v;
}

// ---------------- init (separate tiny kernel; runs before mega) -------------
__global__ void init_kernel() {
    int t = threadIdx.x;
    if (t < T1) { g_cnt_t[t] = 0; g_mk[t] = ~0ULL; }
    if (t == 0) {
        g_bce_sum = 0.f; g_p_sum = 0.f; g_pt_sum = 0.f; g_t_sum = 0.f;
        g_m = 0;
    }
}

// ---------------- the persistent mega kernel ----------------
__global__ void __launch_bounds__(NTHR, 1)
mega_kernel(const float* __restrict__ pred, const int* __restrict__ tgt,
            float* __restrict__ out) {
    const int tid = blockIdx.x * NTHR + threadIdx.x;
    __shared__ int sbins[T1];
    __shared__ int s_used[16];
    __shared__ int s_usedn;

    // ===== Phase 1: base loss + fg + UF init + target histogram =====
    if (threadIdx.x < T1) sbins[threadIdx.x] = 0;
    if (threadIdx.x == 0) s_usedn = 0;
    __syncthreads();

    float a_bce = 0.f, a_p = 0.f, a_pt = 0.f, a_t = 0.f;
    for (int q = tid; q < NPIX / 4; q += NTOT) {          // exactly 2 iters/thread
        int i = q << 2;
        int b = i >> 18;
        int hw = i & (HW - 1);
        const float* bp = pred + (size_t)b * 2 * HW;
        float4 p0v = *(const float4*)(bp + hw);
        float4 p1v = *(const float4*)(bp + HW + hw);
        int4 tv = *(const int4*)(tgt + i);
        int4 pv;
        #define LANE(P0, P1, T, IDX, POUT) {                               \
            bool fg = (P1) > (P0);                                         \
            float y = ((T) > 0) ? 1.f : 0.f;                               \
            if (fg) {                                                      \
                float l = (P1);                                            \
                float e = __expf(-fabsf(l));                               \
                float sp = fmaxf(l, 0.f) + __logf(1.f + e);                \
                float ip = __fdividef(1.f, 1.f + e);                       \
                float p = (l >= 0.f) ? ip : (1.f - ip);                    \
                a_bce += sp - l * y; a_p += p; a_pt += p * y;              \
            } else {                                                       \
                a_bce += SP0F; a_p += 0.5f; a_pt += 0.5f * y;              \
            }                                                              \
            a_t += y;                                                      \
            POUT = fg ? (IDX) : -1;                                        \
            unsigned mm = __match_any_sync(0xFFFFFFFFu, (T));              \
            if ((__ffs(mm) - 1) == (int)(threadIdx.x & 31))                \
                atomicAdd(&sbins[(T)], __popc(mm));                        \
        }
        LANE(p0v.x, p1v.x, tv.x, i + 0, pv.x)
        LANE(p0v.y, p1v.y, tv.y, i + 1, pv.y)
        LANE(p0v.z, p1v.z, tv.z, i + 2, pv.z)
        LANE(p0v.w, p1v.w, tv.w, i + 3, pv.w)
        #undef LANE
        *(int4*)(g_par + i) = pv;
    }
    {
        float4 v = blockReduceSum4(make_float4(a_bce, a_p, a_pt, a_t));
        if (threadIdx.x == 0) {
            atomicAdd(&g_bce_sum, v.x);
            atomicAdd(&g_p_sum,   v.y);
            atomicAdd(&g_pt_sum,  v.z);
            atomicAdd(&g_t_sum,   v.w);
        }
        if (threadIdx.x < T1) atomicAdd(&g_cnt_t[threadIdx.x], sbins[threadIdx.x]);
    }
    grid_barrier();   // 1

    // ===== Phase 2: merge (left & up edges, per image) =====
    for (int i = tid; i < NPIX; i += NTOT) {
        if (g_par[i] < 0) continue;
        int w = i & (WW - 1);
        int h = (i >> 9) & (HH - 1);
        if (w > 0 && g_par[i - 1]  >= 0) uf_unite(i, i - 1);
        if (h > 0 && g_par[i - WW] >= 0) uf_unite(i, i - WW);
    }
    grid_barrier();   // 2

    // ===== Phase 3: compress + compact roots + zero live inter rows =====
    for (int i = tid; i < NPIX; i += NTOT) {
        if (g_par[i] < 0) continue;
        int r = uf_find(i);
        g_par[i] = r;
        if (r == i) {
            int idx = atomicAdd(&g_m, 1);
            g_cidx[i] = idx;
            g_orig[idx] = i;
            #pragma unroll
            for (int t = 0; t < T1; t++) g_intert[(size_t)t * CAP + idx] = 0;
        }
    }
    grid_barrier();   // 3

    // ===== Phase 4: confusion counts =====
    for (int i = tid; i < NPIX; i += NTOT) {
        int r = g_par[i];
        if (r >= 0)
            atomicAdd(&g_intert[(size_t)tgt[i] * CAP + g_cidx[r]], 1);
    }
    grid_barrier();   // 4

    // ===== Phase 5: component sizes (row sums, coalesced) =====
    const int M = g_m;
    for (int c = tid; c < M; c += NTOT) {
        int s = 0;
        #pragma unroll
        for (int t = 0; t < T1; t++) s += g_intert[(size_t)t * CAP + c];
        g_cnt_c[c] = s;
    }
    grid_barrier();   // 5

    // ===== Phase 6: greedy matching (16 iterations, 1 barrier each) =====
    float acc = 0.f, matched = 0.f, untgt = 0.f;   // meaningful on block0/thread0
    for (int t = 1; t < T1; t++) {
        float ct = (float)g_cnt_t[t];
        int un = s_usedn;
        unsigned long long best = ~0ULL;
        for (int c = tid; c < M; c += NTOT) {
            bool skip = false;
            for (int u = 0; u < un; u++) skip |= (s_used[u] == c);
            if (!skip) {
                float cnt_p = (float)g_cnt_c[c];
                float it = (float)g_intert[(size_t)t * CAP + c];
                float bce = (NF * SP0F + cnt_p * C1F - it) / NF;
                float sum_pt = 0.5f * ct + C2F * it;
                float sum_p  = 0.5f * NF + C2F * cnt_p;
                float dice = 1.f - (2.f * sum_pt + 1.f) / ((sum_p + ct) + 1.f);
                float loss = bce + dice;
                unsigned long long key =
                    ((unsigned long long)__float_as_uint(loss) << 32) |
                    (unsigned)g_orig[c];
                best = (key < best) ? key : best;
            }
        }
        best = blockReduceMinU64(best);
        if (threadIdx.x == 0 && best != ~0ULL) atomicMin(&g_mk[t], best);
        grid_barrier();   // 6..21
        if (threadIdx.x == 0) {
            unsigned long long key = g_mk[t];
            bool present = g_cnt_t[t] > 0;
            bool avail = (key != ~0ULL);
            if (present && avail) {
                int orig = (int)(unsigned)(key & 0xFFFFFFFFu);
                s_used[s_usedn] = g_cidx[orig];
                s_usedn = s_usedn + 1;
                if (blockIdx.x == 0) {
                    acc += __uint_as_float((unsigned)(key >> 32));
                    matched += 1.f;
                }
            } else if (present && blockIdx.x == 0) {
                untgt += 1.f;
            }
        }
        __syncthreads();
    }

    // ===== Phase 7: final scalar =====
    if (blockIdx.x == 0 && threadIdx.x == 0) {
        float bce = g_bce_sum / NF;
        float dice = 1.f - (2.f * g_pt_sum + 1.f) / ((g_p_sum + g_t_sum) + 1.f);
        out[0] = (bce + dice) + acc + ((float)M - matched) + untgt;
    }
}

// ---------------- launch ----------------
extern "C" void kernel_launch(void* const* d_in, const int* in_sizes, int n_in,
                              void* d_out, int out_size) {
    const float* pred = (const float*)d_in[0];   // [4,2,512,512] f32
    const int*   tgt  = (const int*)d_in[1];     // [4,1,512,512] i32
    float* out = (float*)d_out;

    init_kernel<<<1, 32>>>();
    mega_kernel<<<NBLK, NTHR>>>(pred, tgt, out);
}

// round 4
// speedup vs baseline: 1.6394x; 1.6394x over previous
#include <cuda_runtime.h>

#define BB 4
#define HH 512
#define WW 512
#define HW (HH*WW)
#define NPIX (BB*HW)             // 1048576
#define T1 17                    // T_MAX + 1
#define CAP 524352               // NPIX/2 + 64, multiple of 4

#define NF 1048576.0f
#define SP0F ((float)0.6931471805599453)
#define C1F  ((float)(1.3132616875182228 - 0.6931471805599453))   // SP1 - SP0
#define C2F  ((float)(0.7310585786300049 - 0.5))                  // S1 - 0.5

// ---------------- device scratch (static, no allocation) ----------------
__device__ __align__(16) int g_par[NPIX];     // UF parent; -1 = background
__device__ int g_cidx[NPIX];                  // root pixel -> compact idx
__device__ int g_orig[CAP];                   // compact idx -> root pixel
__device__ int g_cnt_c[CAP];                  // component sizes
__device__ __align__(16) int g_intert[T1 * CAP];  // transposed confusion [t][c]
__device__ int g_cnt_t[T1];
__device__ int g_m;
__device__ float g_bce_sum, g_p_sum, g_pt_sum, g_t_sum;
__device__ unsigned long long g_mk[T1];

// ---------------- union-find (max-root, path halving; ECL-CC pattern) ------
__device__ __forceinline__ int uf_find(int x) {
    volatile int* par = (volatile int*)g_par;
    int p = par[x];
    while (p != x) {
        int gp = par[p];
        if (gp != p) par[x] = gp;   // halving: stored value always an ancestor
        x = gp;
        p = par[x];
    }
    return x;
}

__device__ __forceinline__ void uf_unite(int a, int b) {
    int ra = uf_find(a);
    int rb = uf_find(b);
    while (ra != rb) {
        if (ra > rb) { int t = ra; ra = rb; rb = t; }  // attach smaller under bigger
        int old = atomicMax(&g_par[ra], rb);
        if (old == ra) break;                           // ra was root: linked
        ra = uf_find(old);
        rb = uf_find(rb);
    }
}

// ---------------- block reductions (256-thread blocks, 8 warps) -------------
__device__ __forceinline__ float4 blockReduceSum4(float4 v) {
    __shared__ float4 s[8];
    unsigned m = 0xFFFFFFFFu;
    #pragma unroll
    for (int o = 16; o; o >>= 1) {
        v.x += __shfl_down_sync(m, v.x, o);
        v.y += __shfl_down_sync(m, v.y, o);
        v.z += __shfl_down_sync(m, v.z, o);
        v.w += __shfl_down_sync(m, v.w, o);
    }
    int lane = threadIdx.x & 31, wid = threadIdx.x >> 5;
    if (lane == 0) s[wid] = v;
    __syncthreads();
    if (wid == 0) {
        v = (lane < 8) ? s[lane] : make_float4(0.f, 0.f, 0.f, 0.f);
        #pragma unroll
        for (int o = 4; o; o >>= 1) {
            v.x += __shfl_down_sync(m, v.x, o);
            v.y += __shfl_down_sync(m, v.y, o);
            v.z += __shfl_down_sync(m, v.z, o);
            v.w += __shfl_down_sync(m, v.w, o);
        }
    }
    return v;
}

__device__ __forceinline__ unsigned long long blockReduceMinU64(unsigned long long v) {
    __shared__ unsigned long long s[8];
    unsigned m = 0xFFFFFFFFu;
    #pragma unroll
    for (int o = 16; o; o >>= 1) {
        unsigned long long o2 = __shfl_down_sync(m, v, o);
        v = (o2 < v) ? o2 : v;
    }
    int lane = threadIdx.x & 31, wid = threadIdx.x >> 5;
    if (lane == 0) s[wid] = v;
    __syncthreads();
    if (wid == 0) {
        v = (lane < 8) ? s[lane] : ~0ULL;
        #pragma unroll
        for (int o = 4; o; o >>= 1) {
            unsigned long long o2 = __shfl_down_sync(m, v, o);
            v = (o2 < v) ? o2 : v;
        }
    }
    return v;
}

// ---------------- kernels ----------------
__global__ void init_kernel() {
    int t = threadIdx.x;
    if (t < T1) { g_cnt_t[t] = 0; g_mk[t] = ~0ULL; }
    if (t == 0) {
        g_bce_sum = 0.f; g_p_sum = 0.f; g_pt_sum = 0.f; g_t_sum = 0.f;
        g_m = 0;
    }
}

// fg + UF init + base BCE/Dice partials + target histogram (1 quad / thread)
__global__ void base_kernel(const float* __restrict__ pred, const int* __restrict__ tgt) {
    __shared__ int sbins[T1];
    if (threadIdx.x < T1) sbins[threadIdx.x] = 0;
    __syncthreads();

    int q = blockIdx.x * blockDim.x + threadIdx.x;   // grid covers NPIX/4 exactly
    int i = q << 2;
    int b = i >> 18;
    int hw = i & (HW - 1);
    const float* bp = pred + (size_t)b * 2 * HW;
    float4 p0v = *(const float4*)(bp + hw);
    float4 p1v = *(const float4*)(bp + HW + hw);
    int4 tv = *(const int4*)(tgt + i);
    int4 pv;
    float a_bce = 0.f, a_p = 0.f, a_pt = 0.f, a_t = 0.f;

    #define LANE(P0, P1, T, IDX, POUT) {                               \
        bool fg = (P1) > (P0);                                         \
        float y = ((T) > 0) ? 1.f : 0.f;                               \
        if (fg) {                                                      \
            float l = (P1);                                            \
            float e = __expf(-fabsf(l));                               \
            float sp = fmaxf(l, 0.f) + __logf(1.f + e);                \
            float ip = __fdividef(1.f, 1.f + e);                       \
            float p = (l >= 0.f) ? ip : (1.f - ip);                    \
            a_bce += sp - l * y; a_p += p; a_pt += p * y;              \
        } else {                                                       \
            a_bce += SP0F; a_p += 0.5f; a_pt += 0.5f * y;              \
        }                                                              \
        a_t += y;                                                      \
        POUT = fg ? (IDX) : -1;                                        \
        unsigned mm = __match_any_sync(0xFFFFFFFFu, (T));              \
        if ((__ffs(mm) - 1) == (int)(threadIdx.x & 31))                \
            atomicAdd(&sbins[(T)], __popc(mm));                        \
    }
    LANE(p0v.x, p1v.x, tv.x, i + 0, pv.x)
    LANE(p0v.y, p1v.y, tv.y, i + 1, pv.y)
    LANE(p0v.z, p1v.z, tv.z, i + 2, pv.z)
    LANE(p0v.w, p1v.w, tv.w, i + 3, pv.w)
    #undef LANE
    *(int4*)(g_par + i) = pv;

    float4 v = blockReduceSum4(make_float4(a_bce, a_p, a_pt, a_t));
    if (threadIdx.x == 0) {
        atomicAdd(&g_bce_sum, v.x);
        atomicAdd(&g_p_sum,   v.y);
        atomicAdd(&g_pt_sum,  v.z);
        atomicAdd(&g_t_sum,   v.w);
    }
    if (threadIdx.x < T1) atomicAdd(&g_cnt_t[threadIdx.x], sbins[threadIdx.x]);
}

// union over left & up edges (per image); 1 pixel / thread
__global__ void merge_kernel() {
    int i = blockIdx.x * blockDim.x + threadIdx.x;
    if (g_par[i] < 0) return;
    int w = i & (WW - 1);
    int h = (i >> 9) & (HH - 1);
    if (w > 0 && g_par[i - 1]  >= 0) uf_unite(i, i - 1);
    if (h > 0 && g_par[i - WW] >= 0) uf_unite(i, i - WW);
}

// flatten to root + compact roots
__global__ void compress_kernel() {
    int i = blockIdx.x * blockDim.x + threadIdx.x;
    if (g_par[i] < 0) return;
    int r = uf_find(i);
    g_par[i] = r;
    if (r == i) {
        int idx = atomicAdd(&g_m, 1);
        g_cidx[i] = idx;
        g_orig[idx] = i;
    }
}

// zero live confusion rows, coalesced (int4)
__global__ void zero_kernel() {
    int M4 = (g_m + 3) >> 2;                  // quads per row (rounded up)
    int tot = T1 * M4;
    int stride = gridDim.x * blockDim.x;
    int4 z = make_int4(0, 0, 0, 0);
    for (int j = blockIdx.x * blockDim.x + threadIdx.x; j < tot; j += stride) {
        int t = j / M4, c4 = j - t * M4;
        *(int4*)(g_intert + t * CAP + (c4 << 2)) = z;
    }
}

// confusion counts with warp aggregation
__global__ void build_kernel(const int* __restrict__ tgt) {
    int i = blockIdx.x * blockDim.x + threadIdx.x;
    int r = g_par[i];
    int t = tgt[i];
    bool fg = r >= 0;
    int c = fg ? g_cidx[r] : 0;
    int key = fg ? (c * T1 + t) : -(int)(threadIdx.x & 31) - 1;  // unique per bg lane
    unsigned mm = __match_any_sync(0xFFFFFFFFu, key);
    if (fg && (__ffs(mm) - 1) == (int)(threadIdx.x & 31))
        atomicAdd(&g_intert[t * CAP + c], __popc(mm));
}

// component sizes = row sums (coalesced)
__global__ void cntc_kernel() {
    int M = g_m;
    int stride = gridDim.x * blockDim.x;
    for (int c = blockIdx.x * blockDim.x + threadIdx.x; c < M; c += stride) {
        int s = 0;
        #pragma unroll
        for (int t = 0; t < T1; t++) s += g_intert[t * CAP + c];
        g_cnt_c[c] = s;
    }
}

// greedy round t: reconstruct used set from prior g_mk, scan, atomicMin winner
__global__ void argmin_kernel(int t) {
    __shared__ int s_uo[16];
    __shared__ int s_un;
    if (threadIdx.x == 0) {
        int un = 0;
        for (int s = 1; s < t; s++) {
            unsigned long long k = g_mk[s];
            if (g_cnt_t[s] > 0 && k != ~0ULL)
                s_uo[un++] = (int)(unsigned)(k & 0xFFFFFFFFu);
        }
        s_un = un;
    }
    __syncthreads();
    const int un = s_un;
    const int M = g_m;
    const float ct = (float)g_cnt_t[t];
    const int stride = gridDim.x * blockDim.x;
    unsigned long long best = ~0ULL;
    for (int c = blockIdx.x * blockDim.x + threadIdx.x; c < M; c += stride) {
        int orig = g_orig[c];
        bool skip = false;
        for (int u = 0; u < un; u++) skip |= (s_uo[u] == orig);
        if (!skip) {
            float cnt_p = (float)g_cnt_c[c];
            float it = (float)g_intert[t * CAP + c];
            float bce = (NF * SP0F + cnt_p * C1F - it) / NF;
            float sum_pt = 0.5f * ct + C2F * it;
            float sum_p  = 0.5f * NF + C2F * cnt_p;
            float dice = 1.f - (2.f * sum_pt + 1.f) / ((sum_p + ct) + 1.f);
            float loss = bce + dice;
            unsigned long long key =
                ((unsigned long long)__float_as_uint(loss) << 32) | (unsigned)orig;
            best = (key < best) ? key : best;
        }
    }
    best = blockReduceMinU64(best);
    if (threadIdx.x == 0 && best != ~0ULL) atomicMin(&g_mk[t], best);
}

// replay greedy decisions + assemble final scalar
__global__ void final_kernel(float* __restrict__ out) {
    float acc = 0.f, matched = 0.f, untgt = 0.f;
    #pragma unroll
    for (int t = 1; t < T1; t++) {
        unsigned long long k = g_mk[t];
        bool present = g_cnt_t[t] > 0;
        bool avail = (k != ~0ULL);
        if (present && avail) {
            acc += __uint_as_float((unsigned)(k >> 32));
            matched += 1.f;
        } else if (present) {
            untgt += 1.f;
        }
    }
    float bce = g_bce_sum / NF;
    float dice = 1.f - (2.f * g_pt_sum + 1.f) / ((g_p_sum + g_t_sum) + 1.f);
    out[0] = (bce + dice) + acc + ((float)g_m - matched) + untgt;
}

// ---------------- launch ----------------
extern "C" void kernel_launch(void* const* d_in, const int* in_sizes, int n_in,
                              void* d_out, int out_size) {
    const float* pred = (const float*)d_in[0];   // [4,2,512,512] f32
    const int*   tgt  = (const int*)d_in[1];     // [4,1,512,512] i32
    float* out = (float*)d_out;

    init_kernel<<<1, 32>>>();
    base_kernel<<<NPIX / 4 / 256, 256>>>(pred, tgt);
    merge_kernel<<<NPIX / 256, 256>>>();
    compress_kernel<<<NPIX / 256, 256>>>();
    zero_kernel<<<512, 256>>>();
    build_kernel<<<NPIX / 256, 256>>>(tgt);
    cntc_kernel<<<256, 256>>>();

    for (int t = 1; t < T1; t++)
        argmin_kernel<<<128, 256>>>(t);
    final_kernel<<<1, 1>>>(out);
}